// round 2
// baseline (speedup 1.0000x reference)
#include <cuda_runtime.h>
#include <cuda_bf16.h>
#include <cstdint>

// Problem constants
#define Bsz   16384
#define INPUT 512
#define HID   1024
#define MEM   1152
#define KV    2
#define SQ    48

// GEMM tiling
#define BM 128
#define BN 128
#define BK 32
#define BKP 36                 // padded K stride (conflict-free fragment loads)
#define ATILE (BM*BKP)         // 4608 floats
#define STAGE_F (2*ATILE)      // A + B tile per stage (BN==BM)
#define NSTAGE 3
#define SMEM_BYTES (NSTAGE*STAGE_F*4)   // 110592 B

#define KT1 (2688/BK)          // 84
#define KT2 (2176/BK)          // 68

// Scratch (device globals are the allowed scratch mechanism)
__device__ float g_y[(size_t)Bsz*HID];      // pre-LN GEMM1 output (64 MB)
__device__ float g_u[(size_t)Bsz*256];      // stage-2 GEMM output, padded stride 256 (16 MB)
__device__ float g_wcat[256*2176];          // packed [W_a;W_b;W_va;W_vb], zero-padded rows
__device__ float g_bcat[256];               // packed biases, zero-padded

// ---------------------------------------------------------------------------
__device__ __forceinline__ uint32_t f2tf(float x) {
    uint32_t r;
    asm("cvt.rna.tf32.f32 %0, %1;" : "=r"(r) : "f"(x));
    return r;
}

__device__ __forceinline__ void mma8(float* c, const uint32_t* a, const uint32_t* b) {
    asm volatile(
        "mma.sync.aligned.m16n8k8.row.col.f32.tf32.tf32.f32 "
        "{%0,%1,%2,%3}, {%4,%5,%6,%7}, {%8,%9}, {%0,%1,%2,%3};\n"
        : "+f"(c[0]), "+f"(c[1]), "+f"(c[2]), "+f"(c[3])
        : "r"(a[0]), "r"(a[1]), "r"(a[2]), "r"(a[3]), "r"(b[0]), "r"(b[1]));
}

__device__ __forceinline__ void cp_async16(float* s, const float* g) {
    uint32_t sa = (uint32_t)__cvta_generic_to_shared(s);
    asm volatile("cp.async.cg.shared.global [%0], [%1], 16;\n" :: "r"(sa), "l"(g));
}
#define CP_COMMIT() asm volatile("cp.async.commit_group;\n" ::: "memory")
#define CP_WAIT2()  asm volatile("cp.async.wait_group 2;\n" ::: "memory")

// ---------------------------------------------------------------------------
// Pack small weights into a single padded 256 x 2176 matrix + bias vector.
__global__ void pack_w_kernel(const float* Wa, const float* ba,
                              const float* Wb, const float* bb,
                              const float* Wva, const float* bva,
                              const float* Wvb, const float* bvb) {
    int idx = blockIdx.x * blockDim.x + threadIdx.x;
    const int total = 196 * 2176;
    if (idx < total) {
        int n = idx / 2176, k = idx - n * 2176;
        const float* src; int r;
        if (n < 2)        { src = Wa;  r = n; }
        else if (n < 4)   { src = Wb;  r = n - 2; }
        else if (n < 100) { src = Wva; r = n - 4; }
        else              { src = Wvb; r = n - 100; }
        g_wcat[n * 2176 + k] = src[(size_t)r * 2176 + k];
    }
    if (idx < 196) {
        int n = idx;
        float v;
        if (n < 2)        v = ba[n];
        else if (n < 4)   v = bb[n - 2];
        else if (n < 100) v = bva[n - 4];
        else              v = bvb[n - 100];
        g_bcat[n] = v;
    }
}

// ---------------------------------------------------------------------------
// GEMM1: Y[m,n] = sum_k c[m,k]*W_h[n,k] + b_h[n], c = [input | h_prev | m_prev]
__global__ __launch_bounds__(256)
void gemm1_kernel(const float* __restrict__ X, const float* __restrict__ H,
                  const float* __restrict__ Mp, const float* __restrict__ W,
                  const float* __restrict__ bias) {
    extern __shared__ float sm[];
    const int tid = threadIdx.x;
    const int bm = blockIdx.y, bn = blockIdx.x;

    auto issue_tile = [&](int t) {
        if (t < KT1) {
            float* base = sm + (t % NSTAGE) * STAGE_F;
            int kt = t * BK;
            const float* src; int ld;
            if (kt < 512)       { src = X + kt;           ld = 512;  }
            else if (kt < 1536) { src = H + (kt - 512);   ld = 1024; }
            else                { src = Mp + (kt - 1536); ld = 1152; }
            src += (size_t)bm * BM * ld;
            #pragma unroll
            for (int i = 0; i < 4; i++) {
                int idx = tid + i * 256;
                int row = idx >> 3, kc = (idx & 7) * 4;
                cp_async16(base + row * BKP + kc, src + (size_t)row * ld + kc);
            }
            const float* ws = W + (size_t)(bn * BN) * 2688 + kt;
            float* bbase = base + ATILE;
            #pragma unroll
            for (int i = 0; i < 4; i++) {
                int idx = tid + i * 256;
                int row = idx >> 3, kc = (idx & 7) * 4;
                cp_async16(bbase + row * BKP + kc, ws + (size_t)row * 2688 + kc);
            }
        }
        CP_COMMIT();
    };

    const int warp = tid >> 5, lane = tid & 31;
    const int wm = warp >> 2, wn = warp & 3;   // 2 x 4 warp grid, warp tile 64x32
    const int lr = lane >> 2, lc = lane & 3;

    float acc[4][4][4];
    #pragma unroll
    for (int i = 0; i < 4; i++)
        #pragma unroll
        for (int j = 0; j < 4; j++)
            #pragma unroll
            for (int q = 0; q < 4; q++) acc[i][j][q] = 0.f;

    issue_tile(0); issue_tile(1);

    for (int t = 0; t < KT1; t++) {
        issue_tile(t + 2);
        CP_WAIT2();
        __syncthreads();
        const float* As = sm + (t % NSTAGE) * STAGE_F;
        const float* Bs = As + ATILE;
        #pragma unroll
        for (int ks = 0; ks < 4; ks++) {
            const int k0 = ks * 8;
            uint32_t a[4][4], b[4][2];
            #pragma unroll
            for (int mi = 0; mi < 4; mi++) {
                const float* p = As + (wm * 64 + mi * 16 + lr) * BKP + k0 + lc;
                a[mi][0] = f2tf(p[0]);
                a[mi][1] = f2tf(p[8 * BKP]);
                a[mi][2] = f2tf(p[4]);
                a[mi][3] = f2tf(p[8 * BKP + 4]);
            }
            #pragma unroll
            for (int ni = 0; ni < 4; ni++) {
                const float* p = Bs + (wn * 32 + ni * 8 + lr) * BKP + k0 + lc;
                b[ni][0] = f2tf(p[0]);
                b[ni][1] = f2tf(p[4]);
            }
            #pragma unroll
            for (int mi = 0; mi < 4; mi++)
                #pragma unroll
                for (int ni = 0; ni < 4; ni++)
                    mma8(acc[mi][ni], a[mi], b[ni]);
        }
        __syncthreads();
    }

    // epilogue: add bias, store to g_y
    #pragma unroll
    for (int mi = 0; mi < 4; mi++) {
        #pragma unroll
        for (int ni = 0; ni < 4; ni++) {
            int r0 = bm * BM + wm * 64 + mi * 16 + lr;
            int c0 = bn * BN + wn * 32 + ni * 8 + 2 * lc;
            float b0 = bias[c0], b1 = bias[c0 + 1];
            float2 v0 = make_float2(acc[mi][ni][0] + b0, acc[mi][ni][1] + b1);
            float2 v1 = make_float2(acc[mi][ni][2] + b0, acc[mi][ni][3] + b1);
            *(float2*)&g_y[(size_t)r0 * HID + c0] = v0;
            *(float2*)&g_y[(size_t)(r0 + 8) * HID + c0] = v1;
        }
    }
}

// ---------------------------------------------------------------------------
// GEMM2: U[m,n] = sum_k hm[m,k]*Wcat[n,k] + bcat[n], hm = [h | m_prev]
__global__ __launch_bounds__(256)
void gemm2_kernel(const float* __restrict__ Hout, const float* __restrict__ Mp) {
    extern __shared__ float sm[];
    const int tid = threadIdx.x;
    const int bm = blockIdx.y, bn = blockIdx.x;

    auto issue_tile = [&](int t) {
        if (t < KT2) {
            float* base = sm + (t % NSTAGE) * STAGE_F;
            int kt = t * BK;
            const float* src; int ld;
            if (kt < 1024) { src = Hout + kt;        ld = 1024; }
            else           { src = Mp + (kt - 1024); ld = 1152; }
            src += (size_t)bm * BM * ld;
            #pragma unroll
            for (int i = 0; i < 4; i++) {
                int idx = tid + i * 256;
                int row = idx >> 3, kc = (idx & 7) * 4;
                cp_async16(base + row * BKP + kc, src + (size_t)row * ld + kc);
            }
            const float* ws = g_wcat + (size_t)(bn * BN) * 2176 + kt;
            float* bbase = base + ATILE;
            #pragma unroll
            for (int i = 0; i < 4; i++) {
                int idx = tid + i * 256;
                int row = idx >> 3, kc = (idx & 7) * 4;
                cp_async16(bbase + row * BKP + kc, ws + (size_t)row * 2176 + kc);
            }
        }
        CP_COMMIT();
    };

    const int warp = tid >> 5, lane = tid & 31;
    const int wm = warp >> 2, wn = warp & 3;
    const int lr = lane >> 2, lc = lane & 3;

    float acc[4][4][4];
    #pragma unroll
    for (int i = 0; i < 4; i++)
        #pragma unroll
        for (int j = 0; j < 4; j++)
            #pragma unroll
            for (int q = 0; q < 4; q++) acc[i][j][q] = 0.f;

    issue_tile(0); issue_tile(1);

    for (int t = 0; t < KT2; t++) {
        issue_tile(t + 2);
        CP_WAIT2();
        __syncthreads();
        const float* As = sm + (t % NSTAGE) * STAGE_F;
        const float* Bs = As + ATILE;
        #pragma unroll
        for (int ks = 0; ks < 4; ks++) {
            const int k0 = ks * 8;
            uint32_t a[4][4], b[4][2];
            #pragma unroll
            for (int mi = 0; mi < 4; mi++) {
                const float* p = As + (wm * 64 + mi * 16 + lr) * BKP + k0 + lc;
                a[mi][0] = f2tf(p[0]);
                a[mi][1] = f2tf(p[8 * BKP]);
                a[mi][2] = f2tf(p[4]);
                a[mi][3] = f2tf(p[8 * BKP + 4]);
            }
            #pragma unroll
            for (int ni = 0; ni < 4; ni++) {
                const float* p = Bs + (wn * 32 + ni * 8 + lr) * BKP + k0 + lc;
                b[ni][0] = f2tf(p[0]);
                b[ni][1] = f2tf(p[4]);
            }
            #pragma unroll
            for (int mi = 0; mi < 4; mi++)
                #pragma unroll
                for (int ni = 0; ni < 4; ni++)
                    mma8(acc[mi][ni], a[mi], b[ni]);
        }
        __syncthreads();
    }

    #pragma unroll
    for (int mi = 0; mi < 4; mi++) {
        #pragma unroll
        for (int ni = 0; ni < 4; ni++) {
            int r0 = bm * BM + wm * 64 + mi * 16 + lr;
            int c0 = bn * BN + wn * 32 + ni * 8 + 2 * lc;
            float b0 = g_bcat[c0], b1 = g_bcat[c0 + 1];
            float2 v0 = make_float2(acc[mi][ni][0] + b0, acc[mi][ni][1] + b1);
            float2 v1 = make_float2(acc[mi][ni][2] + b0, acc[mi][ni][3] + b1);
            *(float2*)&g_u[(size_t)r0 * 256 + c0] = v0;
            *(float2*)&g_u[(size_t)(r0 + 8) * 256 + c0] = v1;
        }
    }
}

// ---------------------------------------------------------------------------
// LayerNorm + ReLU over rows of g_y -> h (d_out region 0)
__global__ __launch_bounds__(256)
void ln_relu_kernel(const float* __restrict__ g, const float* __restrict__ b,
                    float* __restrict__ hout) {
    __shared__ float sa[8], sb[8], smu[2];
    const int row = blockIdx.x, tid = threadIdx.x;
    const int lane = tid & 31, w = tid >> 5;

    float4 v = ((const float4*)(g_y + (size_t)row * HID))[tid];
    float s = v.x + v.y + v.z + v.w;
    float s2 = v.x * v.x + v.y * v.y + v.z * v.z + v.w * v.w;
    #pragma unroll
    for (int o = 16; o; o >>= 1) {
        s  += __shfl_down_sync(0xffffffffu, s, o);
        s2 += __shfl_down_sync(0xffffffffu, s2, o);
    }
    if (!lane) { sa[w] = s; sb[w] = s2; }
    __syncthreads();
    if (w == 0) {
        s  = (lane < 8) ? sa[lane] : 0.f;
        s2 = (lane < 8) ? sb[lane] : 0.f;
        #pragma unroll
        for (int o = 4; o; o >>= 1) {
            s  += __shfl_down_sync(0xffffffffu, s, o);
            s2 += __shfl_down_sync(0xffffffffu, s2, o);
        }
        if (!lane) {
            float mu = s * (1.f / HID);
            float var = s2 * (1.f / HID) - mu * mu;
            smu[0] = mu;
            smu[1] = rsqrtf(var + 1e-5f);
        }
    }
    __syncthreads();
    const float mu = smu[0], inv = smu[1];
    float4 gg = ((const float4*)g)[tid];
    float4 bb = ((const float4*)b)[tid];
    float4 o;
    o.x = fmaxf((v.x - mu) * inv * gg.x + bb.x, 0.f);
    o.y = fmaxf((v.y - mu) * inv * gg.y + bb.y, 0.f);
    o.z = fmaxf((v.z - mu) * inv * gg.z + bb.z, 0.f);
    o.w = fmaxf((v.w - mu) * inv * gg.w + bb.w, 0.f);
    ((float4*)(hout + (size_t)row * HID))[tid] = o;
}

// ---------------------------------------------------------------------------
// Finalize: separable p-norm outer products -> m update
__global__ __launch_bounds__(128)
void finalize_kernel(const float* __restrict__ Mp, float* __restrict__ mout) {
    __shared__ float u[196];
    __shared__ float red[6];
    __shared__ float invn[4];
    __shared__ float cA[24], cB[24];
    const int row = blockIdx.x, tid = threadIdx.x;
    const int w = tid >> 5, lane = tid & 31;

    // NOTE: blockDim == 128 < 196 -> strided load (this was the R1 bug)
    for (int i = tid; i < 196; i += 128) u[i] = g_u[(size_t)row * 256 + i];
    __syncthreads();

    auto p5 = [](float x) { float a = fabsf(x); float a2 = a * a; return a2 * a2 * a; };

    if (w == 0) {                      // S1a_lo / S1a_hi over u1_alpha
        float lo = (lane < 24) ? p5(u[4 + lane]) : 0.f;
        float hi = (lane < 24) ? p5(u[4 + 24 + lane]) : 0.f;
        #pragma unroll
        for (int o = 16; o; o >>= 1) {
            lo += __shfl_down_sync(0xffffffffu, lo, o);
            hi += __shfl_down_sync(0xffffffffu, hi, o);
        }
        if (!lane) { red[0] = lo; red[1] = hi; }
    } else if (w == 1) {               // S2a over u2_alpha (48 vals)
        float x = p5(u[4 + 48 + lane]) + ((lane < 16) ? p5(u[4 + 80 + lane]) : 0.f);
        #pragma unroll
        for (int o = 16; o; o >>= 1) x += __shfl_down_sync(0xffffffffu, x, o);
        if (!lane) red[2] = x;
    } else if (w == 2) {               // S1b_lo / S1b_hi
        float lo = (lane < 24) ? p5(u[100 + lane]) : 0.f;
        float hi = (lane < 24) ? p5(u[100 + 24 + lane]) : 0.f;
        #pragma unroll
        for (int o = 16; o; o >>= 1) {
            lo += __shfl_down_sync(0xffffffffu, lo, o);
            hi += __shfl_down_sync(0xffffffffu, hi, o);
        }
        if (!lane) { red[3] = lo; red[4] = hi; }
    } else {                           // S2b
        float x = p5(u[100 + 48 + lane]) + ((lane < 16) ? p5(u[100 + 80 + lane]) : 0.f);
        #pragma unroll
        for (int o = 16; o; o >>= 1) x += __shfl_down_sync(0xffffffffu, x, o);
        if (!lane) red[5] = x;
    }
    __syncthreads();

    if (tid < 4) {
        float s1 = (tid == 0) ? red[0] : (tid == 1) ? red[1] : (tid == 2) ? red[3] : red[4];
        float s2 = (tid < 2) ? red[2] : red[5];
        float nrm = powf(s1 * s2, 0.2f);
        invn[tid] = 1.f / fmaxf(nrm, 1e-12f);
    }
    __syncthreads();

    if (tid < 24) {
        cA[tid] = 0.5f * (u[0] * u[4 + tid] * invn[0] + u[1] * u[4 + 24 + tid] * invn[1]);
    } else if (tid >= 32 && tid < 56) {
        int i = tid - 32;
        cB[i] = 0.5f * (u[2] * u[100 + i] * invn[2] + u[3] * u[100 + 24 + i] * invn[3]);
    }
    __syncthreads();

    const float* mp = Mp + (size_t)row * MEM;
    float* mo = mout + (size_t)row * MEM;
    #pragma unroll
    for (int j = tid; j < MEM; j += 128) {
        int i = j / 48, j2 = j - i * 48;
        mo[j] = mp[j] + cA[i] * u[52 + j2] - cB[i] * u[148 + j2];
    }
}

// ---------------------------------------------------------------------------
extern "C" void kernel_launch(void* const* d_in, const int* in_sizes, int n_in,
                              void* d_out, int out_size) {
    const float* input  = (const float*)d_in[0];
    const float* h_prev = (const float*)d_in[1];
    const float* m_prev = (const float*)d_in[2];
    const float* W_h    = (const float*)d_in[3];
    const float* b_h    = (const float*)d_in[4];
    const float* ln_g   = (const float*)d_in[5];
    const float* ln_b   = (const float*)d_in[6];
    const float* W_a    = (const float*)d_in[7];
    const float* b_a    = (const float*)d_in[8];
    const float* W_b    = (const float*)d_in[9];
    const float* b_b    = (const float*)d_in[10];
    const float* W_va   = (const float*)d_in[11];
    const float* b_va   = (const float*)d_in[12];
    const float* W_vb   = (const float*)d_in[13];
    const float* b_vb   = (const float*)d_in[14];

    float* out  = (float*)d_out;
    float* hout = out;
    float* mout = out + (size_t)Bsz * HID;

    cudaFuncSetAttribute(gemm1_kernel, cudaFuncAttributeMaxDynamicSharedMemorySize, SMEM_BYTES);
    cudaFuncSetAttribute(gemm2_kernel, cudaFuncAttributeMaxDynamicSharedMemorySize, SMEM_BYTES);

    pack_w_kernel<<<(196 * 2176 + 255) / 256, 256>>>(W_a, b_a, W_b, b_b, W_va, b_va, W_vb, b_vb);
    gemm1_kernel<<<dim3(HID / BN, Bsz / BM), 256, SMEM_BYTES>>>(input, h_prev, m_prev, W_h, b_h);
    ln_relu_kernel<<<Bsz, 256>>>(ln_g, ln_b, hout);
    gemm2_kernel<<<dim3(2, Bsz / BM), 256, SMEM_BYTES>>>(hout, m_prev);
    finalize_kernel<<<Bsz, 128>>>(m_prev, mout);
}